// round 14
// baseline (speedup 1.0000x reference)
#include <cuda_runtime.h>
#include <cuda_fp16.h>
#include <math.h>
#include <stdint.h>

#define C_IN 256
#define HID  128
#define HW   196      // 14*14
#define PHW  49       // 7*7
#define MQ   25088    // 128 * 196
#define MK   6272     // 128 * 49
#define NQ_B 12544
#define NK_B 3136
#define LOG2E 1.4426950408889634f

// ---------------- scratch (device globals) ------------------------------------
__device__ __align__(256) __half g_Aq[MQ * C_IN];        // roisT fp16 [m][c]
__device__ __align__(256) __half g_Ap[MK * C_IN];        // pooled roisT fp16
__device__ __align__(256) __half g_qh[MQ * HID];         // h-permuted
__device__ __align__(256) __half g_kh[MK * HID];         // h-permuted
__device__ __align__(256) __half g_vTh[2 * HID * NK_B];  // [b][h][key], key-permuted
__device__ __align__(256) __half g_wqh[HID * C_IN];      // pre-scaled by log2e
__device__ __align__(256) __half g_wkh[HID * C_IN];
__device__ __align__(256) __half g_wvh[HID * C_IN];
__device__ __align__(256) __half g_wreh[C_IN * HID];

// within-16 permutation: 2t->4t, 2t+1->4t+1, 2t+8->4t+2, 2t+9->4t+3
__device__ __forceinline__ int perm16(int x) {
    return ((x >> 1) & 3) * 4 + (x & 1) + ((x >> 3) << 1);
}

// ---------------- PTX helpers --------------------------------------------------
__device__ __forceinline__ void mma_f16(float& d0, float& d1, float& d2, float& d3,
                                        uint32_t a0, uint32_t a1, uint32_t a2, uint32_t a3,
                                        uint32_t b0, uint32_t b1) {
    asm volatile(
        "mma.sync.aligned.m16n8k16.row.col.f32.f16.f16.f32 "
        "{%0,%1,%2,%3}, {%4,%5,%6,%7}, {%8,%9}, {%0,%1,%2,%3};"
        : "+f"(d0), "+f"(d1), "+f"(d2), "+f"(d3)
        : "r"(a0), "r"(a1), "r"(a2), "r"(a3), "r"(b0), "r"(b1));
}
__device__ __forceinline__ uint32_t smem_u32(const void* p) {
    uint32_t a;
    asm("{ .reg .u64 t; cvta.to.shared.u64 t, %1; cvt.u32.u64 %0, t; }" : "=r"(a) : "l"(p));
    return a;
}
__device__ __forceinline__ void cpasync16(uint32_t dst, const void* src) {
    asm volatile("cp.async.cg.shared.global [%0], [%1], 16;" :: "r"(dst), "l"(src));
}
#define CP_COMMIT() asm volatile("cp.async.commit_group;" ::: "memory")
#define CP_WAIT(N)  asm volatile("cp.async.wait_group %0;" :: "n"(N) : "memory")

// ---------------- prep: one block per (roi, 32-channel chunk) + weight blocks --
__global__ void prep_all(const float* __restrict__ rois,
                         const float* __restrict__ wq, const float* __restrict__ wk,
                         const float* __restrict__ wv, const float* __restrict__ wre) {
    if (blockIdx.x >= 1024) {
        int base = (blockIdx.x - 1024) * 1024 + threadIdx.x;
#pragma unroll
        for (int i = 0; i < 4; i++) {
            int t = base + i * 256;
            g_wqh[t]  = __float2half_rn(wq[t] * LOG2E);
            g_wkh[t]  = __float2half_rn(wk[t]);
            g_wvh[t]  = __float2half_rn(wv[t]);
            g_wreh[t] = __float2half_rn(wre[t]);
        }
        return;
    }
    __shared__ float t[32][197];
    const int n  = blockIdx.x >> 3;
    const int c0 = (blockIdx.x & 7) * 32;
    const int tid = threadIdx.x;

    for (int e = tid; e < 32 * HW; e += 256) {
        int ci = e / HW, p = e - ci * HW;
        t[ci][p] = rois[(n * C_IN + c0 + ci) * HW + p];
    }
    __syncthreads();
    for (int e = tid; e < HW * 16; e += 256) {
        int p = e >> 4, cp = e & 15;
        __half2 h = __floats2half2_rn(t[2 * cp][p], t[2 * cp + 1][p]);
        ((__half2*)g_Aq)[(size_t)(n * HW + p) * 128 + (c0 >> 1) + cp] = h;
    }
    for (int e = tid; e < PHW * 16; e += 256) {
        int pp = e >> 4, cp = e & 15;
        int py = pp / 7, px = pp - py * 7;
        int base = py * 28 + px * 2;
        float a0 = fmaxf(fmaxf(t[2 * cp][base], t[2 * cp][base + 1]),
                         fmaxf(t[2 * cp][base + 14], t[2 * cp][base + 15]));
        float a1 = fmaxf(fmaxf(t[2 * cp + 1][base], t[2 * cp + 1][base + 1]),
                         fmaxf(t[2 * cp + 1][base + 14], t[2 * cp + 1][base + 15]));
        ((__half2*)g_Ap)[(size_t)(n * PHW + pp) * 128 + (c0 >> 1) + cp] = __floats2half2_rn(a0, a1);
    }
}

// ---------------- fused QKV projection GEMM (fp16 HMMA) -----------------------
#define PJ_STRIDE 72
#define PJ_BUF    (128 * PJ_STRIDE)
#define PJ_VST    130
#define PJ_SMEM   (2 * PJ_BUF * 2)

__global__ void __launch_bounds__(256, 4) proj_mma(const float* __restrict__ bq,
                                                   const float* __restrict__ bk,
                                                   const float* __restrict__ bv) {
    extern __shared__ __half psm[];
    const uint32_t psa = smem_u32(psm);

    int bx = blockIdx.x;
    int which, t0;
    if (bx < 196)      { which = 0; t0 = bx; }
    else if (bx < 245) { which = 1; t0 = bx - 196; }
    else               { which = 2; t0 = bx - 245; }
    const __half* A    = which ? g_Ap : g_Aq;
    const __half* W    = which == 0 ? g_wqh : (which == 1 ? g_wkh : g_wvh);
    const float*  bias = which == 0 ? bq    : (which == 1 ? bk    : bv);
    const float   bscale = which == 0 ? LOG2E : 1.0f;
    const int m0 = t0 * 128;

    const int tid  = threadIdx.x;
    const int warp = tid >> 5;
    const int lane = tid & 31;
    const int gr   = lane >> 2;
    const int tg   = lane & 3;
    const int qrow = warp * 16;

    {
        const __half* src = A + (size_t)m0 * C_IN;
#pragma unroll
        for (int i = 0; i < 4; i++) {
            int e = tid + i * 256;
            int row = e >> 3, seg = e & 7;
            cpasync16(psa + (row * PJ_STRIDE + seg * 8) * 2, src + (size_t)row * C_IN + seg * 8);
        }
        CP_COMMIT();
    }

    float y[16][4];
#pragma unroll
    for (int nt = 0; nt < 16; nt++)
#pragma unroll
        for (int j = 0; j < 4; j++) y[nt][j] = 0.f;

    for (int kc = 0; kc < 4; kc++) {
        CP_WAIT(0);
        __syncthreads();
        const __half* sA = psm + (kc & 1) * PJ_BUF;
        if (kc < 3) {
            const __half* src = A + (size_t)m0 * C_IN + (kc + 1) * 64;
            uint32_t dstb = psa + ((kc + 1) & 1) * (PJ_BUF * 2);
#pragma unroll
            for (int i = 0; i < 4; i++) {
                int e = tid + i * 256;
                int row = e >> 3, seg = e & 7;
                cpasync16(dstb + (row * PJ_STRIDE + seg * 8) * 2, src + (size_t)row * C_IN + seg * 8);
            }
            CP_COMMIT();
        }
#pragma unroll
        for (int ks = 0; ks < 4; ks++) {
            int k = kc * 64 + ks * 16;
            uint32_t a0 = *(const uint32_t*)&sA[(qrow + gr) * PJ_STRIDE + ks * 16 + 2 * tg];
            uint32_t a1 = *(const uint32_t*)&sA[(qrow + gr + 8) * PJ_STRIDE + ks * 16 + 2 * tg];
            uint32_t a2 = *(const uint32_t*)&sA[(qrow + gr) * PJ_STRIDE + ks * 16 + 2 * tg + 8];
            uint32_t a3 = *(const uint32_t*)&sA[(qrow + gr + 8) * PJ_STRIDE + ks * 16 + 2 * tg + 8];
#pragma unroll
            for (int nt = 0; nt < 16; nt++) {
                int o = nt * 8 + gr;
                uint32_t b0 = *(const uint32_t*)&W[(size_t)o * C_IN + k + 2 * tg];
                uint32_t b1 = *(const uint32_t*)&W[(size_t)o * C_IN + k + 2 * tg + 8];
                mma_f16(y[nt][0], y[nt][1], y[nt][2], y[nt][3], a0, a1, a2, a3, b0, b1);
            }
        }
        __syncthreads();
    }

    if (which < 2) {
        __half* dst = which == 0 ? g_qh : g_kh;
#pragma unroll
        for (int nt = 0; nt < 16; nt++) {
            int o  = nt * 8 + 2 * tg;
            int hp = (nt >> 1) * 16 + 4 * tg + 2 * (nt & 1);
            float bb0 = bias[o] * bscale, bb1 = bias[o + 1] * bscale;
            *(__half2*)&dst[(size_t)(m0 + qrow + gr) * HID + hp] =
                __floats2half2_rn(y[nt][0] + bb0, y[nt][1] + bb1);
            *(__half2*)&dst[(size_t)(m0 + qrow + gr + 8) * HID + hp] =
                __floats2half2_rn(y[nt][2] + bb0, y[nt][3] + bb1);
        }
    } else {
        __half* sV = psm;
#pragma unroll
        for (int nt = 0; nt < 16; nt++) {
            int o = nt * 8 + 2 * tg;
            float bb0 = bias[o], bb1 = bias[o + 1];
            sV[(qrow + gr) * PJ_VST + o]         = __float2half_rn(y[nt][0] + bb0);
            sV[(qrow + gr) * PJ_VST + o + 1]     = __float2half_rn(y[nt][1] + bb1);
            sV[(qrow + gr + 8) * PJ_VST + o]     = __float2half_rn(y[nt][2] + bb0);
            sV[(qrow + gr + 8) * PJ_VST + o + 1] = __float2half_rn(y[nt][3] + bb1);
        }
        __syncthreads();
#pragma unroll
        for (int i = 0; i < 64; i++) {
            int e = tid + i * 256;
            int h = e >> 7, kk = e & 127;
            int m = m0 + kk;
            int bb = (m >= NK_B) ? 1 : 0;
            int key = m - bb * NK_B;
            int keyp = (key & ~15) | perm16(key & 15);
            g_vTh[(size_t)(bb * HID + h) * NK_B + keyp] = sV[kk * PJ_VST + h];
        }
    }
}

// ---------------- fp16 HMMA flash attention + fused epilogue (BQ=128) ----------
#define SKH_STRIDE 144
#define SK_BUF_H   (64 * SKH_STRIDE)    // 9216 halves
#define SVH_STRIDE 80
#define SV_BUF_H   (128 * SVH_STRIDE)   // 10240 halves
#define SM_V_H     (2 * SK_BUF_H)
#define ATTN_SMEM  ((SM_V_H + 2 * SV_BUF_H) * 2)   // 77824 B
#define ED_STRIDE  129                  // floats; sD = 128 x 129 x 4 = 66048 B

__global__ void __launch_bounds__(256, 2) attn_mma_kernel(const float* __restrict__ rois,
                                                          const float* __restrict__ bre,
                                                          float* __restrict__ out) {
    extern __shared__ __half smh[];
    __half* sK  = smh;
    __half* sVt = smh + SM_V_H;
    float*  sD  = (float*)smh;
    const uint32_t sKa  = smem_u32(sK);
    const uint32_t sVta = smem_u32(sVt);

    const int tid  = threadIdx.x;
    const int warp = tid >> 5;
    const int lane = tid & 31;
    const int gr   = lane >> 2;
    const int tg   = lane & 3;
    const int b    = blockIdx.y;
    const int q0   = blockIdx.x * 128;
    const int qrow = warp * 16;

    const __half* qb = g_qh + (size_t)(b * NQ_B + q0 + qrow) * HID;
    uint32_t qf[8][4];
#pragma unroll
    for (int ks = 0; ks < 8; ks++) {
        uint2 v0 = *(const uint2*)(qb + (size_t)gr * HID + ks * 16 + 4 * tg);
        uint2 v1 = *(const uint2*)(qb + (size_t)(gr + 8) * HID + ks * 16 + 4 * tg);
        qf[ks][0] = v0.x; qf[ks][2] = v0.y;
        qf[ks][1] = v1.x; qf[ks][3] = v1.y;
    }

    const __half* kb0 = g_kh + (size_t)(b * NK_B) * HID;
    const __half* vb0 = g_vTh + (size_t)(b * HID) * NK_B;

    // prefetch chunk 0 (K + V, one group) — 256 threads, 4 chunks each
#pragma unroll
    for (int i = 0; i < 4; i++) {
        int e = tid + i * 256;
        int row = e >> 4, c = e & 15;
        cpasync16(sKa + row * (SKH_STRIDE * 2) + c * 16, kb0 + (size_t)row * HID + c * 8);
    }
#pragma unroll
    for (int i = 0; i < 4; i++) {
        int e = tid + i * 256;
        int row = e >> 3, c = e & 7;
        cpasync16(sVta + row * (SVH_STRIDE * 2) + c * 16, vb0 + (size_t)row * NK_B + c * 8);
    }
    CP_COMMIT();

    float y[16][4];
#pragma unroll
    for (int nt = 0; nt < 16; nt++)
#pragma unroll
        for (int j = 0; j < 4; j++) y[nt][j] = 0.f;
    float m0 = -INFINITY, m1 = -INFINITY;
    float lsum0 = 0.f, lsum1 = 0.f;

    for (int kc = 0; kc < 49; kc++) {
        CP_WAIT(0);
        __syncthreads();

        if (kc < 48) {
            const __half* kb = kb0 + (size_t)((kc + 1) * 64) * HID;
            const __half* vb = vb0 + (kc + 1) * 64;
            uint32_t kdst = sKa + ((kc + 1) & 1) * (SK_BUF_H * 2);
            uint32_t vdst = sVta + ((kc + 1) & 1) * (SV_BUF_H * 2);
#pragma unroll
            for (int i = 0; i < 4; i++) {
                int e = tid + i * 256;
                int row = e >> 4, c = e & 15;
                cpasync16(kdst + row * (SKH_STRIDE * 2) + c * 16, kb + (size_t)row * HID + c * 8);
            }
#pragma unroll
            for (int i = 0; i < 4; i++) {
                int e = tid + i * 256;
                int row = e >> 3, c = e & 7;
                cpasync16(vdst + row * (SVH_STRIDE * 2) + c * 16, vb + (size_t)row * NK_B + c * 8);
            }
            CP_COMMIT();
        }

        const __half* sKb = sK + (kc & 1) * SK_BUF_H;
        const __half* sVb = sVt + (kc & 1) * SV_BUF_H;

        // ---- S = Q K^T ----
        float s[8][4];
#pragma unroll
        for (int nt = 0; nt < 8; nt++)
#pragma unroll
            for (int j = 0; j < 4; j++) s[nt][j] = 0.f;
#pragma unroll
        for (int ks = 0; ks < 8; ks++) {
#pragma unroll
            for (int nt = 0; nt < 8; nt++) {
                uint2 kv = *(const uint2*)&sKb[(nt * 8 + gr) * SKH_STRIDE + ks * 16 + 4 * tg];
                mma_f16(s[nt][0], s[nt][1], s[nt][2], s[nt][3],
                        qf[ks][0], qf[ks][1], qf[ks][2], qf[ks][3], kv.x, kv.y);
            }
        }

        // ---- running row max (base-2), conditional rescale ----
        float mx0 = -INFINITY, mx1 = -INFINITY;
#pragma unroll
        for (int nt = 0; nt < 8; nt++) {
            mx0 = fmaxf(mx0, fmaxf(s[nt][0], s[nt][1]));
            mx1 = fmaxf(mx1, fmaxf(s[nt][2], s[nt][3]));
        }
        mx0 = fmaxf(mx0, __shfl_xor_sync(0xffffffffu, mx0, 1));
        mx0 = fmaxf(mx0, __shfl_xor_sync(0xffffffffu, mx0, 2));
        mx1 = fmaxf(mx1, __shfl_xor_sync(0xffffffffu, mx1, 1));
        mx1 = fmaxf(mx1, __shfl_xor_sync(0xffffffffu, mx1, 2));
        bool grew = (mx0 > m0) || (mx1 > m1);
        if (__any_sync(0xffffffffu, grew)) {
            float mn0 = fmaxf(m0, mx0);
            float mn1 = fmaxf(m1, mx1);
            float corr0 = exp2f(m0 - mn0);
            float corr1 = exp2f(m1 - mn1);
            m0 = mn0; m1 = mn1;
            lsum0 *= corr0; lsum1 *= corr1;
#pragma unroll
            for (int nt = 0; nt < 16; nt++) {
                y[nt][0] *= corr0; y[nt][1] *= corr0;
                y[nt][2] *= corr1; y[nt][3] *= corr1;
            }
        }

        uint32_t pa[4][4];
#pragma unroll
        for (int nt = 0; nt < 8; nt++) {
            float p0 = exp2f(s[nt][0] - m0);
            float p1 = exp2f(s[nt][1] - m0);
            float p2 = exp2f(s[nt][2] - m1);
            float p3 = exp2f(s[nt][3] - m1);
            lsum0 += p0 + p1;
            lsum1 += p2 + p3;
            __half2 h01 = __floats2half2_rn(p0, p1);
            __half2 h23 = __floats2half2_rn(p2, p3);
            int kp = nt >> 1;
            if ((nt & 1) == 0) { pa[kp][0] = *(uint32_t*)&h01; pa[kp][1] = *(uint32_t*)&h23; }
            else               { pa[kp][2] = *(uint32_t*)&h01; pa[kp][3] = *(uint32_t*)&h23; }
        }

        // ---- Y += P V ----
#pragma unroll
        for (int ks = 0; ks < 4; ks++) {
#pragma unroll
            for (int nt = 0; nt < 16; nt++) {
                uint2 vv = *(const uint2*)&sVb[(nt * 8 + gr) * SVH_STRIDE + ks * 16 + 4 * tg];
                mma_f16(y[nt][0], y[nt][1], y[nt][2], y[nt][3],
                        pa[ks][0], pa[ks][1], pa[ks][2], pa[ks][3], vv.x, vv.y);
            }
        }
    }

    // ---- rowsum normalize, convert Y -> fp16 A-fragments ----
#pragma unroll
    for (int off = 1; off < 4; off <<= 1) {
        lsum0 += __shfl_xor_sync(0xffffffffu, lsum0, off);
        lsum1 += __shfl_xor_sync(0xffffffffu, lsum1, off);
    }
    const float inv0 = 1.0f / lsum0;
    const float inv1 = 1.0f / lsum1;

    uint32_t pya[8][4];
#pragma unroll
    for (int ks = 0; ks < 8; ks++) {
        __half2 h0 = __floats2half2_rn(y[2 * ks][0] * inv0, y[2 * ks][1] * inv0);
        __half2 h1 = __floats2half2_rn(y[2 * ks][2] * inv1, y[2 * ks][3] * inv1);
        __half2 h2 = __floats2half2_rn(y[2 * ks + 1][0] * inv0, y[2 * ks + 1][1] * inv0);
        __half2 h3 = __floats2half2_rn(y[2 * ks + 1][2] * inv1, y[2 * ks + 1][3] * inv1);
        pya[ks][0] = *(uint32_t*)&h0;
        pya[ks][1] = *(uint32_t*)&h1;
        pya[ks][2] = *(uint32_t*)&h2;
        pya[ks][3] = *(uint32_t*)&h3;
    }

    __syncthreads();   // all warps done with K/V smem -> sD may reuse it

    // ---- fused epilogue: out = rois + Y * wre^T + bre, two n-halves -----------
    const int mb = b * NQ_B + q0;      // global m base of this CTA's 128 rows
#pragma unroll 1
    for (int half = 0; half < 2; half++) {
        const int n0 = half * 128;

        float ye[16][4];
#pragma unroll
        for (int nt = 0; nt < 16; nt++)
#pragma unroll
            for (int j = 0; j < 4; j++) ye[nt][j] = 0.f;

#pragma unroll
        for (int ks = 0; ks < 8; ks++) {
            int k = ks * 16;
#pragma unroll
            for (int nt = 0; nt < 16; nt++) {
                int o = n0 + nt * 8 + gr;
                uint32_t b0 = *(const uint32_t*)&g_wreh[(size_t)o * HID + k + 2 * tg];
                uint32_t b1 = *(const uint32_t*)&g_wreh[(size_t)o * HID + k + 2 * tg + 8];
                mma_f16(ye[nt][0], ye[nt][1], ye[nt][2], ye[nt][3],
                        pya[ks][0], pya[ks][1], pya[ks][2], pya[ks][3], b0, b1);
            }
        }

        // stage D (128 rows of this CTA)
#pragma unroll
        for (int nt = 0; nt < 16; nt++) {
            int o = nt * 8 + 2 * tg;
            sD[(qrow + gr) * ED_STRIDE + o]         = ye[nt][0];
            sD[(qrow + gr) * ED_STRIDE + o + 1]     = ye[nt][1];
            sD[(qrow + gr + 8) * ED_STRIDE + o]     = ye[nt][2];
            sD[(qrow + gr + 8) * ED_STRIDE + o + 1] = ye[nt][3];
        }
        __syncthreads();

        // coalesced residual add + store (128 rows x 128 channels)
#pragma unroll 4
        for (int i = 0; i < 64; i++) {
            int e = tid + i * 256;
            int o = e >> 7, ml = e & 127;
            int mg = mb + ml;
            int n = mg / HW;
            int p = mg - n * HW;
            int co = n0 + o;
            size_t idx = (size_t)(n * C_IN + co) * HW + p;
            out[idx] = rois[idx] + sD[ml * ED_STRIDE + o] + bre[co];
        }
        __syncthreads();
    }
}

// ---------------- launch ------------------------------------------------------
extern "C" void kernel_launch(void* const* d_in, const int* in_sizes, int n_in,
                              void* d_out, int out_size) {
    const float* rois = (const float*)d_in[0];
    const float* wq  = (const float*)d_in[2];
    const float* bq  = (const float*)d_in[3];
    const float* wk  = (const float*)d_in[4];
    const float* bk  = (const float*)d_in[5];
    const float* wv  = (const float*)d_in[6];
    const float* bv  = (const float*)d_in[7];
    const float* wre = (const float*)d_in[8];
    const float* bre = (const float*)d_in[9];
    float* out = (float*)d_out;

    cudaFuncSetAttribute(attn_mma_kernel, cudaFuncAttributeMaxDynamicSharedMemorySize, ATTN_SMEM);
    cudaFuncSetAttribute(proj_mma, cudaFuncAttributeMaxDynamicSharedMemorySize, PJ_SMEM);

    prep_all<<<1056, 256>>>(rois, wq, wk, wv, wre);
    proj_mma<<<294, 256, PJ_SMEM>>>(bq, bk, bv);
    attn_mma_kernel<<<dim3(98, 2), 256, ATTN_SMEM>>>(rois, bre, out);
}

// round 15
// speedup vs baseline: 1.3143x; 1.3143x over previous
#include <cuda_runtime.h>
#include <cuda_fp16.h>
#include <math.h>
#include <stdint.h>

#define C_IN 256
#define HID  128
#define HW   196      // 14*14
#define PHW  49       // 7*7
#define MQ   25088    // 128 * 196
#define MK   6272     // 128 * 49
#define NQ_B 12544
#define NK_B 3136
#define LOG2E 1.4426950408889634f

// ---------------- scratch (device globals) ------------------------------------
__device__ __align__(256) __half g_Aq[MQ * C_IN];        // roisT fp16 [m][c], c perm16
__device__ __align__(256) __half g_Ap[MK * C_IN];        // pooled, c perm16
__device__ __align__(256) __half g_qh[MQ * HID];         // h-permuted
__device__ __align__(256) __half g_kh[MK * HID];         // h-permuted
__device__ __align__(256) __half g_vTh[2 * HID * NK_B];  // [b][h][key], key-permuted
__device__ __align__(256) __half g_wqh[HID * C_IN];      // k perm16, pre-scaled log2e
__device__ __align__(256) __half g_wkh[HID * C_IN];      // k perm16
__device__ __align__(256) __half g_wvh[HID * C_IN];      // k perm16
__device__ __align__(256) __half g_wreh[C_IN * HID];     // k(h) perm16

// within-16 permutation: 2t->4t, 2t+1->4t+1, 2t+8->4t+2, 2t+9->4t+3
__device__ __forceinline__ int perm16(int x) {
    return ((x >> 1) & 3) * 4 + (x & 1) + ((x >> 3) << 1);
}

// ---------------- PTX helpers --------------------------------------------------
__device__ __forceinline__ void mma_f16(float& d0, float& d1, float& d2, float& d3,
                                        uint32_t a0, uint32_t a1, uint32_t a2, uint32_t a3,
                                        uint32_t b0, uint32_t b1) {
    asm volatile(
        "mma.sync.aligned.m16n8k16.row.col.f32.f16.f16.f32 "
        "{%0,%1,%2,%3}, {%4,%5,%6,%7}, {%8,%9}, {%0,%1,%2,%3};"
        : "+f"(d0), "+f"(d1), "+f"(d2), "+f"(d3)
        : "r"(a0), "r"(a1), "r"(a2), "r"(a3), "r"(b0), "r"(b1));
}
__device__ __forceinline__ uint32_t smem_u32(const void* p) {
    uint32_t a;
    asm("{ .reg .u64 t; cvta.to.shared.u64 t, %1; cvt.u32.u64 %0, t; }" : "=r"(a) : "l"(p));
    return a;
}
__device__ __forceinline__ void cpasync16(uint32_t dst, const void* src) {
    asm volatile("cp.async.cg.shared.global [%0], [%1], 16;" :: "r"(dst), "l"(src));
}
#define CP_COMMIT() asm volatile("cp.async.commit_group;" ::: "memory")
#define CP_WAIT(N)  asm volatile("cp.async.wait_group %0;" :: "n"(N) : "memory")

// ---------------- prep: one block per (roi, 32-channel chunk) + weight blocks --
__global__ void prep_all(const float* __restrict__ rois,
                         const float* __restrict__ wq, const float* __restrict__ wk,
                         const float* __restrict__ wv, const float* __restrict__ wre) {
    if (blockIdx.x >= 1024) {
        int base = (blockIdx.x - 1024) * 1024 + threadIdx.x;
#pragma unroll
        for (int i = 0; i < 4; i++) {
            int t = base + i * 256;
            // wq/wk/wv: [o][c], permute c within 16-groups
            int o = t >> 8, c = t & 255;
            int cperm = (c & ~15) | perm16(c & 15);
            g_wqh[o * C_IN + cperm] = __float2half_rn(wq[t] * LOG2E);
            g_wkh[o * C_IN + cperm] = __float2half_rn(wk[t]);
            g_wvh[o * C_IN + cperm] = __float2half_rn(wv[t]);
            // wre: [co][h], permute h within 16-groups
            int co = t >> 7, h = t & 127;
            int hperm = (h & ~15) | perm16(h & 15);
            g_wreh[co * HID + hperm] = __float2half_rn(wre[t]);
        }
        return;
    }
    __shared__ float t[32][197];
    const int n  = blockIdx.x >> 3;
    const int c0 = (blockIdx.x & 7) * 32;
    const int tid = threadIdx.x;

    for (int e = tid; e < 32 * HW; e += 256) {
        int ci = e / HW, p = e - ci * HW;
        t[ci][p] = rois[(n * C_IN + c0 + ci) * HW + p];
    }
    __syncthreads();
    for (int e = tid; e < HW * 16; e += 256) {
        int p = e >> 4, cp = e & 15;
        int P = (c0 >> 1) + cp;                    // global pair index
        int q = P & 7;
        int P2 = (P & ~7) | ((q < 4) ? (2 * q) : (2 * (q - 4) + 1));
        __half2 h = __floats2half2_rn(t[2 * cp][p], t[2 * cp + 1][p]);
        ((__half2*)g_Aq)[(size_t)(n * HW + p) * 128 + P2] = h;
    }
    for (int e = tid; e < PHW * 16; e += 256) {
        int pp = e >> 4, cp = e & 15;
        int py = pp / 7, px = pp - py * 7;
        int base = py * 28 + px * 2;
        float a0 = fmaxf(fmaxf(t[2 * cp][base], t[2 * cp][base + 1]),
                         fmaxf(t[2 * cp][base + 14], t[2 * cp][base + 15]));
        float a1 = fmaxf(fmaxf(t[2 * cp + 1][base], t[2 * cp + 1][base + 1]),
                         fmaxf(t[2 * cp + 1][base + 14], t[2 * cp + 1][base + 15]));
        int P = (c0 >> 1) + cp;
        int q = P & 7;
        int P2 = (P & ~7) | ((q < 4) ? (2 * q) : (2 * (q - 4) + 1));
        ((__half2*)g_Ap)[(size_t)(n * PHW + pp) * 128 + P2] = __floats2half2_rn(a0, a1);
    }
}

// ---------------- fused QKV projection GEMM (fp16 HMMA, uint2 frags) -----------
#define PJ_STRIDE 80
#define PJ_BUF    (128 * PJ_STRIDE)
#define PJ_VST    130
#define PJ_SMEM   (2 * PJ_BUF * 2)     // 40960 B

__global__ void __launch_bounds__(256, 4) proj_mma(const float* __restrict__ bq,
                                                   const float* __restrict__ bk,
                                                   const float* __restrict__ bv) {
    extern __shared__ __half psm[];
    const uint32_t psa = smem_u32(psm);

    int bx = blockIdx.x;
    int which, t0;
    if (bx < 196)      { which = 0; t0 = bx; }
    else if (bx < 245) { which = 1; t0 = bx - 196; }
    else               { which = 2; t0 = bx - 245; }
    const __half* A    = which ? g_Ap : g_Aq;
    const __half* W    = which == 0 ? g_wqh : (which == 1 ? g_wkh : g_wvh);
    const float*  bias = which == 0 ? bq    : (which == 1 ? bk    : bv);
    const float   bscale = which == 0 ? LOG2E : 1.0f;
    const int m0 = t0 * 128;

    const int tid  = threadIdx.x;
    const int warp = tid >> 5;
    const int lane = tid & 31;
    const int gr   = lane >> 2;
    const int tg   = lane & 3;
    const int qrow = warp * 16;

    {
        const __half* src = A + (size_t)m0 * C_IN;
#pragma unroll
        for (int i = 0; i < 4; i++) {
            int e = tid + i * 256;
            int row = e >> 3, seg = e & 7;
            cpasync16(psa + (row * PJ_STRIDE + seg * 8) * 2, src + (size_t)row * C_IN + seg * 8);
        }
        CP_COMMIT();
    }

    float y[16][4];
#pragma unroll
    for (int nt = 0; nt < 16; nt++)
#pragma unroll
        for (int j = 0; j < 4; j++) y[nt][j] = 0.f;

    for (int kc = 0; kc < 4; kc++) {
        CP_WAIT(0);
        __syncthreads();
        const __half* sA = psm + (kc & 1) * PJ_BUF;
        if (kc < 3) {
            const __half* src = A + (size_t)m0 * C_IN + (kc + 1) * 64;
            uint32_t dstb = psa + ((kc + 1) & 1) * (PJ_BUF * 2);
#pragma unroll
            for (int i = 0; i < 4; i++) {
                int e = tid + i * 256;
                int row = e >> 3, seg = e & 7;
                cpasync16(dstb + (row * PJ_STRIDE + seg * 8) * 2, src + (size_t)row * C_IN + seg * 8);
            }
            CP_COMMIT();
        }
#pragma unroll
        for (int ks = 0; ks < 4; ks++) {
            int k = kc * 64 + ks * 16;
            uint2 av0 = *(const uint2*)&sA[(qrow + gr) * PJ_STRIDE + ks * 16 + 4 * tg];
            uint2 av1 = *(const uint2*)&sA[(qrow + gr + 8) * PJ_STRIDE + ks * 16 + 4 * tg];
#pragma unroll
            for (int nt = 0; nt < 16; nt++) {
                int o = nt * 8 + gr;
                uint2 wv2 = *(const uint2*)&W[(size_t)o * C_IN + k + 4 * tg];
                mma_f16(y[nt][0], y[nt][1], y[nt][2], y[nt][3],
                        av0.x, av1.x, av0.y, av1.y, wv2.x, wv2.y);
            }
        }
        __syncthreads();
    }

    if (which < 2) {
        __half* dst = which == 0 ? g_qh : g_kh;
#pragma unroll
        for (int nt = 0; nt < 16; nt++) {
            int o  = nt * 8 + 2 * tg;
            int hp = (nt >> 1) * 16 + 4 * tg + 2 * (nt & 1);
            float bb0 = bias[o] * bscale, bb1 = bias[o + 1] * bscale;
            *(__half2*)&dst[(size_t)(m0 + qrow + gr) * HID + hp] =
                __floats2half2_rn(y[nt][0] + bb0, y[nt][1] + bb1);
            *(__half2*)&dst[(size_t)(m0 + qrow + gr + 8) * HID + hp] =
                __floats2half2_rn(y[nt][2] + bb0, y[nt][3] + bb1);
        }
    } else {
        __half* sV = psm;
#pragma unroll
        for (int nt = 0; nt < 16; nt++) {
            int o = nt * 8 + 2 * tg;
            float bb0 = bias[o], bb1 = bias[o + 1];
            sV[(qrow + gr) * PJ_VST + o]         = __float2half_rn(y[nt][0] + bb0);
            sV[(qrow + gr) * PJ_VST + o + 1]     = __float2half_rn(y[nt][1] + bb1);
            sV[(qrow + gr + 8) * PJ_VST + o]     = __float2half_rn(y[nt][2] + bb0);
            sV[(qrow + gr + 8) * PJ_VST + o + 1] = __float2half_rn(y[nt][3] + bb1);
        }
        __syncthreads();
#pragma unroll
        for (int i = 0; i < 64; i++) {
            int e = tid + i * 256;
            int h = e >> 7, kk = e & 127;
            int m = m0 + kk;
            int bb = (m >= NK_B) ? 1 : 0;
            int key = m - bb * NK_B;
            int keyp = (key & ~15) | perm16(key & 15);
            g_vTh[(size_t)(bb * HID + h) * NK_B + keyp] = sV[kk * PJ_VST + h];
        }
    }
}

// ---------------- fp16 HMMA flash attention + fused epilogue (BQ=64) -----------
#define SKH_STRIDE 144
#define SK_BUF_H   (64 * SKH_STRIDE)    // 9216 halves
#define SVH_STRIDE 80
#define SV_BUF_H   (128 * SVH_STRIDE)   // 10240 halves
#define SM_V_H     (2 * SK_BUF_H)
#define ATTN_SMEM  ((SM_V_H + 2 * SV_BUF_H) * 2)   // 77824 B
#define ED_STRIDE  129

__global__ void __launch_bounds__(128, 2) attn_mma_kernel(const float* __restrict__ rois,
                                                          const float* __restrict__ bre,
                                                          float* __restrict__ out) {
    extern __shared__ __half smh[];
    __half* sK  = smh;
    __half* sVt = smh + SM_V_H;
    float*  sD  = (float*)smh;
    const uint32_t sKa  = smem_u32(sK);
    const uint32_t sVta = smem_u32(sVt);

    const int tid  = threadIdx.x;
    const int warp = tid >> 5;
    const int lane = tid & 31;
    const int gr   = lane >> 2;
    const int tg   = lane & 3;
    const int b    = blockIdx.y;
    const int q0   = blockIdx.x * 64;
    const int qrow = warp * 16;

    const __half* qb = g_qh + (size_t)(b * NQ_B + q0 + qrow) * HID;
    uint32_t qf[8][4];
#pragma unroll
    for (int ks = 0; ks < 8; ks++) {
        uint2 v0 = *(const uint2*)(qb + (size_t)gr * HID + ks * 16 + 4 * tg);
        uint2 v1 = *(const uint2*)(qb + (size_t)(gr + 8) * HID + ks * 16 + 4 * tg);
        qf[ks][0] = v0.x; qf[ks][2] = v0.y;
        qf[ks][1] = v1.x; qf[ks][3] = v1.y;
    }

    const __half* kb0 = g_kh + (size_t)(b * NK_B) * HID;
    const __half* vb0 = g_vTh + (size_t)(b * HID) * NK_B;

#pragma unroll
    for (int i = 0; i < 8; i++) {
        int e = tid + i * 128;
        int row = e >> 4, c = e & 15;
        cpasync16(sKa + row * (SKH_STRIDE * 2) + c * 16, kb0 + (size_t)row * HID + c * 8);
    }
#pragma unroll
    for (int i = 0; i < 8; i++) {
        int e = tid + i * 128;
        int row = e >> 3, c = e & 7;
        cpasync16(sVta + row * (SVH_STRIDE * 2) + c * 16, vb0 + (size_t)row * NK_B + c * 8);
    }
    CP_COMMIT();

    float y[16][4];
#pragma unroll
    for (int nt = 0; nt < 16; nt++)
#pragma unroll
        for (int j = 0; j < 4; j++) y[nt][j] = 0.f;
    float m0 = -INFINITY, m1 = -INFINITY;
    float lsum0 = 0.f, lsum1 = 0.f;

    for (int kc = 0; kc < 49; kc++) {
        CP_WAIT(0);
        __syncthreads();

        if (kc < 48) {
            const __half* kb = kb0 + (size_t)((kc + 1) * 64) * HID;
            const __half* vb = vb0 + (kc + 1) * 64;
            uint32_t kdst = sKa + ((kc + 1) & 1) * (SK_BUF_H * 2);
            uint32_t vdst = sVta + ((kc + 1) & 1) * (SV_BUF_H * 2);
#pragma unroll
            for (int i = 0; i < 8; i++) {
                int e = tid + i * 128;
                int row = e >> 4, c = e & 15;
                cpasync16(kdst + row * (SKH_STRIDE * 2) + c * 16, kb + (size_t)row * HID + c * 8);
            }
#pragma unroll
            for (int i = 0; i < 8; i++) {
                int e = tid + i * 128;
                int row = e >> 3, c = e & 7;
                cpasync16(vdst + row * (SVH_STRIDE * 2) + c * 16, vb + (size_t)row * NK_B + c * 8);
            }
            CP_COMMIT();
        }

        const __half* sKb = sK + (kc & 1) * SK_BUF_H;
        const __half* sVb = sVt + (kc & 1) * SV_BUF_H;

        float s[8][4];
#pragma unroll
        for (int nt = 0; nt < 8; nt++)
#pragma unroll
            for (int j = 0; j < 4; j++) s[nt][j] = 0.f;
#pragma unroll
        for (int ks = 0; ks < 8; ks++) {
#pragma unroll
            for (int nt = 0; nt < 8; nt++) {
                uint2 kv = *(const uint2*)&sKb[(nt * 8 + gr) * SKH_STRIDE + ks * 16 + 4 * tg];
                mma_f16(s[nt][0], s[nt][1], s[nt][2], s[nt][3],
                        qf[ks][0], qf[ks][1], qf[ks][2], qf[ks][3], kv.x, kv.y);
            }
        }

        float mx0 = -INFINITY, mx1 = -INFINITY;
#pragma unroll
        for (int nt = 0; nt < 8; nt++) {
            mx0 = fmaxf(mx0, fmaxf(s[nt][0], s[nt][1]));
            mx1 = fmaxf(mx1, fmaxf(s[nt][2], s[nt][3]));
        }
        mx0 = fmaxf(mx0, __shfl_xor_sync(0xffffffffu, mx0, 1));
        mx0 = fmaxf(mx0, __shfl_xor_sync(0xffffffffu, mx0, 2));
        mx1 = fmaxf(mx1, __shfl_xor_sync(0xffffffffu, mx1, 1));
        mx1 = fmaxf(mx1, __shfl_xor_sync(0xffffffffu, mx1, 2));
        bool grew = (mx0 > m0) || (mx1 > m1);
        if (__any_sync(0xffffffffu, grew)) {
            float mn0 = fmaxf(m0, mx0);
            float mn1 = fmaxf(m1, mx1);
            float corr0 = exp2f(m0 - mn0);
            float corr1 = exp2f(m1 - mn1);
            m0 = mn0; m1 = mn1;
            lsum0 *= corr0; lsum1 *= corr1;
#pragma unroll
            for (int nt = 0; nt < 16; nt++) {
                y[nt][0] *= corr0; y[nt][1] *= corr0;
                y[nt][2] *= corr1; y[nt][3] *= corr1;
            }
        }

        uint32_t pa[4][4];
#pragma unroll
        for (int nt = 0; nt < 8; nt++) {
            float p0 = exp2f(s[nt][0] - m0);
            float p1 = exp2f(s[nt][1] - m0);
            float p2 = exp2f(s[nt][2] - m1);
            float p3 = exp2f(s[nt][3] - m1);
            lsum0 += p0 + p1;
            lsum1 += p2 + p3;
            __half2 h01 = __floats2half2_rn(p0, p1);
            __half2 h23 = __floats2half2_rn(p2, p3);
            int kp = nt >> 1;
            if ((nt & 1) == 0) { pa[kp][0] = *(uint32_t*)&h01; pa[kp][1] = *(uint32_t*)&h23; }
            else               { pa[kp][2] = *(uint32_t*)&h01; pa[kp][3] = *(uint32_t*)&h23; }
        }

#pragma unroll
        for (int ks = 0; ks < 4; ks++) {
#pragma unroll
            for (int nt = 0; nt < 16; nt++) {
                uint2 vv = *(const uint2*)&sVb[(nt * 8 + gr) * SVH_STRIDE + ks * 16 + 4 * tg];
                mma_f16(y[nt][0], y[nt][1], y[nt][2], y[nt][3],
                        pa[ks][0], pa[ks][1], pa[ks][2], pa[ks][3], vv.x, vv.y);
            }
        }
    }

#pragma unroll
    for (int off = 1; off < 4; off <<= 1) {
        lsum0 += __shfl_xor_sync(0xffffffffu, lsum0, off);
        lsum1 += __shfl_xor_sync(0xffffffffu, lsum1, off);
    }
    const float inv0 = 1.0f / lsum0;
    const float inv1 = 1.0f / lsum1;

    uint32_t pya[8][4];
#pragma unroll
    for (int ks = 0; ks < 8; ks++) {
        __half2 h0 = __floats2half2_rn(y[2 * ks][0] * inv0, y[2 * ks][1] * inv0);
        __half2 h1 = __floats2half2_rn(y[2 * ks][2] * inv1, y[2 * ks][3] * inv1);
        __half2 h2 = __floats2half2_rn(y[2 * ks + 1][0] * inv0, y[2 * ks + 1][1] * inv0);
        __half2 h3 = __floats2half2_rn(y[2 * ks + 1][2] * inv1, y[2 * ks + 1][3] * inv1);
        pya[ks][0] = *(uint32_t*)&h0;
        pya[ks][1] = *(uint32_t*)&h1;
        pya[ks][2] = *(uint32_t*)&h2;
        pya[ks][3] = *(uint32_t*)&h3;
    }

    __syncthreads();

    const int mb = b * NQ_B + q0;
#pragma unroll 1
    for (int half = 0; half < 2; half++) {
        const int n0 = half * 128;

        float ye[16][4];
#pragma unroll
        for (int nt = 0; nt < 16; nt++)
#pragma unroll
            for (int j = 0; j < 4; j++) ye[nt][j] = 0.f;

#pragma unroll
        for (int ks = 0; ks < 8; ks++) {
            int k = ks * 16;
#pragma unroll
            for (int nt = 0; nt < 16; nt++) {
                int o = n0 + nt * 8 + gr;
                uint2 wv2 = *(const uint2*)&g_wreh[(size_t)o * HID + k + 4 * tg];
                mma_f16(ye[nt][0], ye[nt][1], ye[nt][2], ye[nt][3],
                        pya[ks][0], pya[ks][1], pya[ks][2], pya[ks][3], wv2.x, wv2.y);
            }
        }

#pragma unroll
        for (int nt = 0; nt < 16; nt++) {
            int o = nt * 8 + 2 * tg;
            sD[(qrow + gr) * ED_STRIDE + o]         = ye[nt][0];
            sD[(qrow + gr) * ED_STRIDE + o + 1]     = ye[nt][1];
            sD[(qrow + gr + 8) * ED_STRIDE + o]     = ye[nt][2];
            sD[(qrow + gr + 8) * ED_STRIDE + o + 1] = ye[nt][3];
        }
        __syncthreads();

#pragma unroll 4
        for (int i = 0; i < 64; i++) {
            int e = tid + i * 128;
            int o = e >> 6, ml = e & 63;
            int mg = mb + ml;
            int n = mg / HW;
            int p = mg - n * HW;
            int co = n0 + o;
            size_t idx = (size_t)(n * C_IN + co) * HW + p;
            out[idx] = rois[idx] + sD[ml * ED_STRIDE + o] + bre[co];
        }
        __syncthreads();
    }
}

// ---------------- launch ------------------------------------------------------
extern "C" void kernel_launch(void* const* d_in, const int* in_sizes, int n_in,
                              void* d_out, int out_size) {
    const float* rois = (const float*)d_in[0];
    const float* wq  = (const float*)d_in[2];
    const float* bq  = (const float*)d_in[3];
    const float* wk  = (const float*)d_in[4];
    const float* bk  = (const float*)d_in[5];
    const float* wv  = (const float*)d_in[6];
    const float* bv  = (const float*)d_in[7];
    const float* wre = (const float*)d_in[8];
    const float* bre = (const float*)d_in[9];
    float* out = (float*)d_out;

    cudaFuncSetAttribute(attn_mma_kernel, cudaFuncAttributeMaxDynamicSharedMemorySize, ATTN_SMEM);
    cudaFuncSetAttribute(proj_mma, cudaFuncAttributeMaxDynamicSharedMemorySize, PJ_SMEM);

    prep_all<<<1056, 256>>>(rois, wq, wk, wv, wre);
    proj_mma<<<294, 256, PJ_SMEM>>>(bq, bk, bv);
    attn_mma_kernel<<<dim3(196, 2), 128, ATTN_SMEM>>>(rois, bre, out);
}

// round 16
// speedup vs baseline: 1.4057x; 1.0695x over previous
#include <cuda_runtime.h>
#include <cuda_fp16.h>
#include <math.h>
#include <stdint.h>

#define C_IN 256
#define HID  128
#define HW   196      // 14*14
#define PHW  49       // 7*7
#define MQ   25088    // 128 * 196
#define MK   6272     // 128 * 49
#define NQ_B 12544
#define NK_B 3136
#define LOG2E 1.4426950408889634f

// ---------------- scratch (device globals) ------------------------------------
__device__ __align__(256) __half g_Aq[MQ * C_IN];        // roisT fp16 [m][c], c perm16
__device__ __align__(256) __half g_Ap[MK * C_IN];        // pooled, c perm16
__device__ __align__(256) __half g_qh[MQ * HID];         // h-permuted, row-major
__device__ __align__(256) __half g_kh[MK * HID];         // fragment-major chunks
__device__ __align__(256) __half g_vTh[2 * HID * NK_B];  // fragment-major chunks
__device__ __align__(256) __half g_wqh[HID * C_IN];      // k perm16, pre-scaled log2e
__device__ __align__(256) __half g_wkh[HID * C_IN];      // k perm16
__device__ __align__(256) __half g_wvh[HID * C_IN];      // k perm16
__device__ __align__(256) __half g_wreh[C_IN * HID];     // k(h) perm16

// within-16 permutation: 2t->4t, 2t+1->4t+1, 2t+8->4t+2, 2t+9->4t+3
__device__ __forceinline__ int perm16(int x) {
    return ((x >> 1) & 3) * 4 + (x & 1) + ((x >> 3) << 1);
}
// K chunk fragment-major offset: (kk 0..63, hp 0..127) -> half offset in 8192 chunk
__device__ __forceinline__ int ak_off(int kk, int hp) {
    return ((((hp >> 4) * 4 + (kk >> 4)) * 32) + (kk & 7) * 4 + ((hp >> 2) & 3)) * 8
           + ((kk >> 3) & 1) * 4 + (hp & 3);
}
// V chunk fragment-major offset: (h 0..127, kp 0..63) -> half offset in 8192 chunk
__device__ __forceinline__ int av_off(int h, int kp) {
    return ((((kp >> 4) * 8 + (h >> 4)) * 32) + (h & 7) * 4 + ((kp >> 2) & 3)) * 8
           + ((h >> 3) & 1) * 4 + (kp & 3);
}

// ---------------- PTX helpers --------------------------------------------------
__device__ __forceinline__ void mma_f16(float& d0, float& d1, float& d2, float& d3,
                                        uint32_t a0, uint32_t a1, uint32_t a2, uint32_t a3,
                                        uint32_t b0, uint32_t b1) {
    asm volatile(
        "mma.sync.aligned.m16n8k16.row.col.f32.f16.f16.f32 "
        "{%0,%1,%2,%3}, {%4,%5,%6,%7}, {%8,%9}, {%0,%1,%2,%3};"
        : "+f"(d0), "+f"(d1), "+f"(d2), "+f"(d3)
        : "r"(a0), "r"(a1), "r"(a2), "r"(a3), "r"(b0), "r"(b1));
}
__device__ __forceinline__ uint32_t smem_u32(const void* p) {
    uint32_t a;
    asm("{ .reg .u64 t; cvta.to.shared.u64 t, %1; cvt.u32.u64 %0, t; }" : "=r"(a) : "l"(p));
    return a;
}
__device__ __forceinline__ void cpasync16(uint32_t dst, const void* src) {
    asm volatile("cp.async.cg.shared.global [%0], [%1], 16;" :: "r"(dst), "l"(src));
}
#define CP_COMMIT() asm volatile("cp.async.commit_group;" ::: "memory")
#define CP_WAIT(N)  asm volatile("cp.async.wait_group %0;" :: "n"(N) : "memory")

// ---------------- prep: one block per (roi, 32-channel chunk) + weight blocks --
__global__ void prep_all(const float* __restrict__ rois,
                         const float* __restrict__ wq, const float* __restrict__ wk,
                         const float* __restrict__ wv, const float* __restrict__ wre) {
    if (blockIdx.x >= 1024) {
        int base = (blockIdx.x - 1024) * 1024 + threadIdx.x;
#pragma unroll
        for (int i = 0; i < 4; i++) {
            int t = base + i * 256;
            int o = t >> 8, c = t & 255;
            int cperm = (c & ~15) | perm16(c & 15);
            g_wqh[o * C_IN + cperm] = __float2half_rn(wq[t] * LOG2E);
            g_wkh[o * C_IN + cperm] = __float2half_rn(wk[t]);
            g_wvh[o * C_IN + cperm] = __float2half_rn(wv[t]);
            int co = t >> 7, h = t & 127;
            int hperm = (h & ~15) | perm16(h & 15);
            g_wreh[co * HID + hperm] = __float2half_rn(wre[t]);
        }
        return;
    }
    __shared__ float t[32][197];
    const int n  = blockIdx.x >> 3;
    const int c0 = (blockIdx.x & 7) * 32;
    const int tid = threadIdx.x;

    for (int e = tid; e < 32 * HW; e += 256) {
        int ci = e / HW, p = e - ci * HW;
        t[ci][p] = rois[(n * C_IN + c0 + ci) * HW + p];
    }
    __syncthreads();
    for (int e = tid; e < HW * 16; e += 256) {
        int p = e >> 4, cp = e & 15;
        int P = (c0 >> 1) + cp;
        int q = P & 7;
        int P2 = (P & ~7) | ((q < 4) ? (2 * q) : (2 * (q - 4) + 1));
        __half2 h = __floats2half2_rn(t[2 * cp][p], t[2 * cp + 1][p]);
        ((__half2*)g_Aq)[(size_t)(n * HW + p) * 128 + P2] = h;
    }
    for (int e = tid; e < PHW * 16; e += 256) {
        int pp = e >> 4, cp = e & 15;
        int py = pp / 7, px = pp - py * 7;
        int base = py * 28 + px * 2;
        float a0 = fmaxf(fmaxf(t[2 * cp][base], t[2 * cp][base + 1]),
                         fmaxf(t[2 * cp][base + 14], t[2 * cp][base + 15]));
        float a1 = fmaxf(fmaxf(t[2 * cp + 1][base], t[2 * cp + 1][base + 1]),
                         fmaxf(t[2 * cp + 1][base + 14], t[2 * cp + 1][base + 15]));
        int P = (c0 >> 1) + cp;
        int q = P & 7;
        int P2 = (P & ~7) | ((q < 4) ? (2 * q) : (2 * (q - 4) + 1));
        ((__half2*)g_Ap)[(size_t)(n * PHW + pp) * 128 + P2] = __floats2half2_rn(a0, a1);
    }
}

// ---------------- fused QKV projection GEMM (fp16 HMMA, uint2 frags) -----------
#define PJ_STRIDE 80
#define PJ_BUF    (128 * PJ_STRIDE)
#define PJ_VST    130
#define PJ_SMEM   (2 * PJ_BUF * 2)     // 40960 B

__global__ void __launch_bounds__(256, 4) proj_mma(const float* __restrict__ bq,
                                                   const float* __restrict__ bk,
                                                   const float* __restrict__ bv) {
    extern __shared__ __half psm[];
    const uint32_t psa = smem_u32(psm);

    int bx = blockIdx.x;
    int which, t0;
    if (bx < 196)      { which = 0; t0 = bx; }
    else if (bx < 245) { which = 1; t0 = bx - 196; }
    else               { which = 2; t0 = bx - 245; }
    const __half* A    = which ? g_Ap : g_Aq;
    const __half* W    = which == 0 ? g_wqh : (which == 1 ? g_wkh : g_wvh);
    const float*  bias = which == 0 ? bq    : (which == 1 ? bk    : bv);
    const float   bscale = which == 0 ? LOG2E : 1.0f;
    const int m0 = t0 * 128;

    const int tid  = threadIdx.x;
    const int warp = tid >> 5;
    const int lane = tid & 31;
    const int gr   = lane >> 2;
    const int tg   = lane & 3;
    const int qrow = warp * 16;

    {
        const __half* src = A + (size_t)m0 * C_IN;
#pragma unroll
        for (int i = 0; i < 4; i++) {
            int e = tid + i * 256;
            int row = e >> 3, seg = e & 7;
            cpasync16(psa + (row * PJ_STRIDE + seg * 8) * 2, src + (size_t)row * C_IN + seg * 8);
        }
        CP_COMMIT();
    }

    float y[16][4];
#pragma unroll
    for (int nt = 0; nt < 16; nt++)
#pragma unroll
        for (int j = 0; j < 4; j++) y[nt][j] = 0.f;

    for (int kc = 0; kc < 4; kc++) {
        CP_WAIT(0);
        __syncthreads();
        const __half* sA = psm + (kc & 1) * PJ_BUF;
        if (kc < 3) {
            const __half* src = A + (size_t)m0 * C_IN + (kc + 1) * 64;
            uint32_t dstb = psa + ((kc + 1) & 1) * (PJ_BUF * 2);
#pragma unroll
            for (int i = 0; i < 4; i++) {
                int e = tid + i * 256;
                int row = e >> 3, seg = e & 7;
                cpasync16(dstb + (row * PJ_STRIDE + seg * 8) * 2, src + (size_t)row * C_IN + seg * 8);
            }
            CP_COMMIT();
        }
#pragma unroll
        for (int ks = 0; ks < 4; ks++) {
            int k = kc * 64 + ks * 16;
            uint2 av0 = *(const uint2*)&sA[(qrow + gr) * PJ_STRIDE + ks * 16 + 4 * tg];
            uint2 av1 = *(const uint2*)&sA[(qrow + gr + 8) * PJ_STRIDE + ks * 16 + 4 * tg];
#pragma unroll
            for (int nt = 0; nt < 16; nt++) {
                int o = nt * 8 + gr;
                uint2 wv2 = *(const uint2*)&W[(size_t)o * C_IN + k + 4 * tg];
                mma_f16(y[nt][0], y[nt][1], y[nt][2], y[nt][3],
                        av0.x, av1.x, av0.y, av1.y, wv2.x, wv2.y);
            }
        }
        __syncthreads();
    }

    if (which == 0) {
        // Q: row-major, h-permuted
#pragma unroll
        for (int nt = 0; nt < 16; nt++) {
            int o  = nt * 8 + 2 * tg;
            int hp = (nt >> 1) * 16 + 4 * tg + 2 * (nt & 1);
            float bb0 = bias[o] * bscale, bb1 = bias[o + 1] * bscale;
            *(__half2*)&g_qh[(size_t)(m0 + qrow + gr) * HID + hp] =
                __floats2half2_rn(y[nt][0] + bb0, y[nt][1] + bb1);
            *(__half2*)&g_qh[(size_t)(m0 + qrow + gr + 8) * HID + hp] =
                __floats2half2_rn(y[nt][2] + bb0, y[nt][3] + bb1);
        }
    } else if (which == 1) {
        // K: fragment-major chunks
        int m1 = m0 + qrow + gr;
        int m2 = m1 + 8;
        int bb1_ = (m1 >= NK_B), bb2_ = (m2 >= NK_B);
        int key1 = m1 - bb1_ * NK_B, key2 = m2 - bb2_ * NK_B;
        __half* c1 = g_kh + (size_t)(bb1_ * 49 + (key1 >> 6)) * 8192;
        __half* c2 = g_kh + (size_t)(bb2_ * 49 + (key2 >> 6)) * 8192;
        int kk1 = key1 & 63, kk2 = key2 & 63;
#pragma unroll
        for (int nt = 0; nt < 16; nt++) {
            int o  = nt * 8 + 2 * tg;
            int hp = (nt >> 1) * 16 + 4 * tg + 2 * (nt & 1);
            float bb0 = bias[o], bb1 = bias[o + 1];
            *(__half2*)&c1[ak_off(kk1, hp)] = __floats2half2_rn(y[nt][0] + bb0, y[nt][1] + bb1);
            *(__half2*)&c2[ak_off(kk2, hp)] = __floats2half2_rn(y[nt][2] + bb0, y[nt][3] + bb1);
        }
    } else {
        // V: stage then fragment-major scatter
        __half* sV = psm;
#pragma unroll
        for (int nt = 0; nt < 16; nt++) {
            int o = nt * 8 + 2 * tg;
            float bb0 = bias[o], bb1 = bias[o + 1];
            sV[(qrow + gr) * PJ_VST + o]         = __float2half_rn(y[nt][0] + bb0);
            sV[(qrow + gr) * PJ_VST + o + 1]     = __float2half_rn(y[nt][1] + bb1);
            sV[(qrow + gr + 8) * PJ_VST + o]     = __float2half_rn(y[nt][2] + bb0);
            sV[(qrow + gr + 8) * PJ_VST + o + 1] = __float2half_rn(y[nt][3] + bb1);
        }
        __syncthreads();
#pragma unroll
        for (int i = 0; i < 64; i++) {
            int e = tid + i * 256;
            int h = e >> 7, kk0 = e & 127;
            int m = m0 + kk0;
            int bb = (m >= NK_B) ? 1 : 0;
            int key = m - bb * NK_B;
            int kk = key & 63;
            int kkp = (kk & ~15) | perm16(kk & 15);
            g_vTh[(size_t)(bb * 49 + (key >> 6)) * 8192 + av_off(h, kkp)] = sV[kk0 * PJ_VST + h];
        }
    }
}

// ---------------- fp16 HMMA flash attention + fused epilogue (BQ=64) -----------
#define SK_BUF_H   8192                 // halves per K chunk
#define SV_BUF_H   8192                 // halves per V chunk
#define SM_V_H     (2 * SK_BUF_H)
#define ATTN_SMEM  ((SM_V_H + 2 * SV_BUF_H) * 2)   // 65536 B
#define ED_STRIDE  129

__global__ void __launch_bounds__(128, 2) attn_mma_kernel(const float* __restrict__ rois,
                                                          const float* __restrict__ bre,
                                                          float* __restrict__ out) {
    extern __shared__ __half smh[];
    __half* sK  = smh;
    __half* sVt = smh + SM_V_H;
    float*  sD  = (float*)smh;
    const uint32_t sKa  = smem_u32(sK);
    const uint32_t sVta = smem_u32(sVt);

    const int tid  = threadIdx.x;
    const int warp = tid >> 5;
    const int lane = tid & 31;
    const int gr   = lane >> 2;
    const int tg   = lane & 3;
    const int b    = blockIdx.y;
    const int q0   = blockIdx.x * 64;
    const int qrow = warp * 16;

    const __half* qb = g_qh + (size_t)(b * NQ_B + q0 + qrow) * HID;
    uint32_t qf[8][4];
#pragma unroll
    for (int ks = 0; ks < 8; ks++) {
        uint2 v0 = *(const uint2*)(qb + (size_t)gr * HID + ks * 16 + 4 * tg);
        uint2 v1 = *(const uint2*)(qb + (size_t)(gr + 8) * HID + ks * 16 + 4 * tg);
        qf[ks][0] = v0.x; qf[ks][2] = v0.y;
        qf[ks][1] = v1.x; qf[ks][3] = v1.y;
    }

    const __half* kb0 = g_kh + (size_t)(b * 49) * 8192;
    const __half* vb0 = g_vTh + (size_t)(b * 49) * 8192;

#pragma unroll
    for (int i = 0; i < 8; i++) {
        int e = tid + i * 128;
        cpasync16(sKa + e * 16, kb0 + e * 8);
    }
#pragma unroll
    for (int i = 0; i < 8; i++) {
        int e = tid + i * 128;
        cpasync16(sVta + e * 16, vb0 + e * 8);
    }
    CP_COMMIT();

    float y[16][4];
#pragma unroll
    for (int nt = 0; nt < 16; nt++)
#pragma unroll
        for (int j = 0; j < 4; j++) y[nt][j] = 0.f;
    float m0 = -INFINITY, m1 = -INFINITY;
    float lsum0 = 0.f, lsum1 = 0.f;

    for (int kc = 0; kc < 49; kc++) {
        CP_WAIT(0);
        __syncthreads();

        if (kc < 48) {
            const __half* kb = kb0 + (size_t)(kc + 1) * 8192;
            const __half* vb = vb0 + (size_t)(kc + 1) * 8192;
            uint32_t kdst = sKa + ((kc + 1) & 1) * (SK_BUF_H * 2);
            uint32_t vdst = sVta + ((kc + 1) & 1) * (SV_BUF_H * 2);
#pragma unroll
            for (int i = 0; i < 8; i++) {
                int e = tid + i * 128;
                cpasync16(kdst + e * 16, kb + e * 8);
            }
#pragma unroll
            for (int i = 0; i < 8; i++) {
                int e = tid + i * 128;
                cpasync16(vdst + e * 16, vb + e * 8);
            }
            CP_COMMIT();
        }

        const uint4* sK4 = (const uint4*)(sK + (kc & 1) * SK_BUF_H);
        const uint4* sV4 = (const uint4*)(sVt + (kc & 1) * SV_BUF_H);

        // ---- S = Q K^T : uint4 -> 2 MMAs ----
        float s[8][4];
#pragma unroll
        for (int nt = 0; nt < 8; nt++)
#pragma unroll
            for (int j = 0; j < 4; j++) s[nt][j] = 0.f;
#pragma unroll
        for (int ks = 0; ks < 8; ks++) {
#pragma unroll
            for (int ntp = 0; ntp < 4; ntp++) {
                uint4 kv = sK4[(ks * 4 + ntp) * 32 + lane];
                mma_f16(s[2 * ntp][0], s[2 * ntp][1], s[2 * ntp][2], s[2 * ntp][3],
                        qf[ks][0], qf[ks][1], qf[ks][2], qf[ks][3], kv.x, kv.y);
                mma_f16(s[2 * ntp + 1][0], s[2 * ntp + 1][1], s[2 * ntp + 1][2], s[2 * ntp + 1][3],
                        qf[ks][0], qf[ks][1], qf[ks][2], qf[ks][3], kv.z, kv.w);
            }
        }

        // ---- running row max (base-2), conditional rescale ----
        float mx0 = -INFINITY, mx1 = -INFINITY;
#pragma unroll
        for (int nt = 0; nt < 8; nt++) {
            mx0 = fmaxf(mx0, fmaxf(s[nt][0], s[nt][1]));
            mx1 = fmaxf(mx1, fmaxf(s[nt][2], s[nt][3]));
        }
        mx0 = fmaxf(mx0, __shfl_xor_sync(0xffffffffu, mx0, 1));
        mx0 = fmaxf(mx0, __shfl_xor_sync(0xffffffffu, mx0, 2));
        mx1 = fmaxf(mx1, __shfl_xor_sync(0xffffffffu, mx1, 1));
        mx1 = fmaxf(mx1, __shfl_xor_sync(0xffffffffu, mx1, 2));
        bool grew = (mx0 > m0) || (mx1 > m1);
        if (__any_sync(0xffffffffu, grew)) {
            float mn0 = fmaxf(m0, mx0);
            float mn1 = fmaxf(m1, mx1);
            float corr0 = exp2f(m0 - mn0);
            float corr1 = exp2f(m1 - mn1);
            m0 = mn0; m1 = mn1;
            lsum0 *= corr0; lsum1 *= corr1;
#pragma unroll
            for (int nt = 0; nt < 16; nt++) {
                y[nt][0] *= corr0; y[nt][1] *= corr0;
                y[nt][2] *= corr1; y[nt][3] *= corr1;
            }
        }

        uint32_t pa[4][4];
#pragma unroll
        for (int nt = 0; nt < 8; nt++) {
            float p0 = exp2f(s[nt][0] - m0);
            float p1 = exp2f(s[nt][1] - m0);
            float p2 = exp2f(s[nt][2] - m1);
            float p3 = exp2f(s[nt][3] - m1);
            lsum0 += p0 + p1;
            lsum1 += p2 + p3;
            __half2 h01 = __floats2half2_rn(p0, p1);
            __half2 h23 = __floats2half2_rn(p2, p3);
            int kp = nt >> 1;
            if ((nt & 1) == 0) { pa[kp][0] = *(uint32_t*)&h01; pa[kp][1] = *(uint32_t*)&h23; }
            else               { pa[kp][2] = *(uint32_t*)&h01; pa[kp][3] = *(uint32_t*)&h23; }
        }

        // ---- Y += P V : uint4 -> 2 MMAs ----
#pragma unroll
        for (int ks = 0; ks < 4; ks++) {
#pragma unroll
            for (int ntp = 0; ntp < 8; ntp++) {
                uint4 vv = sV4[(ks * 8 + ntp) * 32 + lane];
                mma_f16(y[2 * ntp][0], y[2 * ntp][1], y[2 * ntp][2], y[2 * ntp][3],
                        pa[ks][0], pa[ks][1], pa[ks][2], pa[ks][3], vv.x, vv.y);
                mma_f16(y[2 * ntp + 1][0], y[2 * ntp + 1][1], y[2 * ntp + 1][2], y[2 * ntp + 1][3],
                        pa[ks][0], pa[ks][1], pa[ks][2], pa[ks][3], vv.z, vv.w);
            }
        }
    }

#pragma unroll
    for (int off = 1; off < 4; off <<= 1) {
        lsum0 += __shfl_xor_sync(0xffffffffu, lsum0, off);
        lsum1 += __shfl_xor_sync(0xffffffffu, lsum1, off);
    }
    const float inv0 = 1.0f / lsum0;
    const float inv1 = 1.0f / lsum1;

    uint32_t pya[8][4];
#pragma unroll
    for (int ks = 0; ks < 8; ks++) {
        __half2 h0 = __floats2half2_rn(y[2 * ks][0] * inv0, y[2 * ks][1] * inv0);
        __half2 h1 = __floats2half2_rn(y[2 * ks][2] * inv1, y[2 * ks][3] * inv1);
        __half2 h2 = __floats2half2_rn(y[2 * ks + 1][0] * inv0, y[2 * ks + 1][1] * inv0);
        __half2 h3 = __floats2half2_rn(y[2 * ks + 1][2] * inv1, y[2 * ks + 1][3] * inv1);
        pya[ks][0] = *(uint32_t*)&h0;
        pya[ks][1] = *(uint32_t*)&h1;
        pya[ks][2] = *(uint32_t*)&h2;
        pya[ks][3] = *(uint32_t*)&h3;
    }

    __syncthreads();

    const int mb = b * NQ_B + q0;
#pragma unroll 1
    for (int half = 0; half < 2; half++) {
        const int n0 = half * 128;

        float ye[16][4];
#pragma unroll
        for (int nt = 0; nt < 16; nt++)
#pragma unroll
            for (int j = 0; j < 4; j++) ye[nt][j] = 0.f;

#pragma unroll
        for (int ks = 0; ks < 8; ks++) {
            int k = ks * 16;
#pragma unroll
            for (int nt = 0; nt < 16; nt++) {
                int o = n0 + nt * 8 + gr;
                uint2 wv2 = *(const uint2*)&g_wreh[(size_t)o * HID + k + 4 * tg];
                mma_f16(ye[nt][0], ye[nt][1], ye[nt][2], ye[nt][3],
                        pya[ks][0], pya[ks][1], pya[ks][2], pya[ks][3], wv2.x, wv2.y);
            }
        }

#pragma unroll
        for (int nt = 0; nt < 16; nt++) {
            int o = nt * 8 + 2 * tg;
            sD[(qrow + gr) * ED_STRIDE + o]         = ye[nt][0];
            sD[(qrow + gr) * ED_STRIDE + o + 1]     = ye[nt][1];
            sD[(qrow + gr + 8) * ED_STRIDE + o]     = ye[nt][2];
            sD[(qrow + gr + 8) * ED_STRIDE + o + 1] = ye[nt][3];
        }
        __syncthreads();

#pragma unroll 4
        for (int i = 0; i < 64; i++) {
            int e = tid + i * 128;
            int o = e >> 6, ml = e & 63;
            int mg = mb + ml;
            int n = mg / HW;
            int p = mg - n * HW;
            int co = n0 + o;
            size_t idx = (size_t)(n * C_IN + co) * HW + p;
            out[idx] = rois[idx] + sD[ml * ED_STRIDE + o] + bre[co];
        }
        __syncthreads();
    }
}

// ---------------- launch ------------------------------------------------------
extern "C" void kernel_launch(void* const* d_in, const int* in_sizes, int n_in,
                              void* d_out, int out_size) {
    const float* rois = (const float*)d_in[0];
    const float* wq  = (const float*)d_in[2];
    const float* bq  = (const float*)d_in[3];
    const float* wk  = (const float*)d_in[4];
    const float* bk  = (const float*)d_in[5];
    const float* wv  = (const float*)d_in[6];
    const float* bv  = (const float*)d_in[7];
    const float* wre = (const float*)d_in[8];
    const float* bre = (const float*)d_in[9];
    float* out = (float*)d_out;

    cudaFuncSetAttribute(attn_mma_kernel, cudaFuncAttributeMaxDynamicSharedMemorySize, ATTN_SMEM);
    cudaFuncSetAttribute(proj_mma, cudaFuncAttributeMaxDynamicSharedMemorySize, PJ_SMEM);

    prep_all<<<1056, 256>>>(rois, wq, wk, wv, wre);
    proj_mma<<<294, 256, PJ_SMEM>>>(bq, bk, bv);
    attn_mma_kernel<<<dim3(196, 2), 128, ATTN_SMEM>>>(rois, bre, out);
}

// round 17
// speedup vs baseline: 1.4503x; 1.0317x over previous
#include <cuda_runtime.h>
#include <cuda_fp16.h>
#include <math.h>
#include <stdint.h>

#define C_IN 256
#define HID  128
#define HW   196      // 14*14
#define PHW  49       // 7*7
#define MQ   25088    // 128 * 196
#define MK   6272     // 128 * 49
#define NQ_B 12544
#define NK_B 3136
#define LOG2E 1.4426950408889634f

// ---------------- scratch (device globals) ------------------------------------
__device__ __align__(256) __half g_Aq[MQ * C_IN];        // roisT fp16 [m][c], c perm16
__device__ __align__(256) __half g_Ap[MK * C_IN];        // pooled, c perm16
__device__ __align__(256) __half g_qh[MQ * HID];         // h-permuted, row-major
__device__ __align__(256) __half g_kh[MK * HID];         // fragment-major chunks
__device__ __align__(256) __half g_vTh[2 * HID * NK_B];  // fragment-major chunks
__device__ __align__(256) __half g_wqh[HID * C_IN];      // k perm16, pre-scaled log2e
__device__ __align__(256) __half g_wkh[HID * C_IN];      // k perm16
__device__ __align__(256) __half g_wvh[HID * C_IN];      // k perm16
__device__ __align__(256) __half g_wreh[C_IN * HID];     // fragment-major

// within-16 permutation: 2t->4t, 2t+1->4t+1, 2t+8->4t+2, 2t+9->4t+3
__device__ __forceinline__ int perm16(int x) {
    return ((x >> 1) & 3) * 4 + (x & 1) + ((x >> 3) << 1);
}
// K chunk fragment-major offset: (kk 0..63, hp 0..127) -> half offset in 8192 chunk
__device__ __forceinline__ int ak_off(int kk, int hp) {
    return ((((hp >> 4) * 4 + (kk >> 4)) * 32) + (kk & 7) * 4 + ((hp >> 2) & 3)) * 8
           + ((kk >> 3) & 1) * 4 + (hp & 3);
}
// V chunk fragment-major offset: (h 0..127, kp 0..63) -> half offset in 8192 chunk
__device__ __forceinline__ int av_off(int h, int kp) {
    return ((((kp >> 4) * 8 + (h >> 4)) * 32) + (h & 7) * 4 + ((kp >> 2) & 3)) * 8
           + ((h >> 3) & 1) * 4 + (kp & 3);
}
// wre fragment-major offset: (o 0..255, hp 0..127) -> half offset
__device__ __forceinline__ int wre_off(int o, int hp) {
    int nh = o >> 7, o7 = o & 127;
    int ntp = o7 >> 4, rsel = (o7 >> 3) & 1, grr = o7 & 7;
    int ks = hp >> 4, tgg = (hp >> 2) & 3, c = hp & 3;
    return ((((nh * 8 + ks) * 8 + ntp) * 32) + grr * 4 + tgg) * 8 + rsel * 4 + c;
}

// ---------------- PTX helpers --------------------------------------------------
__device__ __forceinline__ void mma_f16(float& d0, float& d1, float& d2, float& d3,
                                        uint32_t a0, uint32_t a1, uint32_t a2, uint32_t a3,
                                        uint32_t b0, uint32_t b1) {
    asm volatile(
        "mma.sync.aligned.m16n8k16.row.col.f32.f16.f16.f32 "
        "{%0,%1,%2,%3}, {%4,%5,%6,%7}, {%8,%9}, {%0,%1,%2,%3};"
        : "+f"(d0), "+f"(d1), "+f"(d2), "+f"(d3)
        : "r"(a0), "r"(a1), "r"(a2), "r"(a3), "r"(b0), "r"(b1));
}
// packed exp2: returns half2 {lo=2^lo, hi=2^hi}
__device__ __forceinline__ uint32_t h2exp2(float lo, float hi) {
    uint32_t r;
    asm("{\n\t.reg .b32 t;\n\tcvt.rn.f16x2.f32 t, %2, %1;\n\tex2.approx.f16x2 %0, t;\n\t}"
        : "=r"(r) : "f"(lo), "f"(hi));
    return r;
}
__device__ __forceinline__ uint32_t smem_u32(const void* p) {
    uint32_t a;
    asm("{ .reg .u64 t; cvta.to.shared.u64 t, %1; cvt.u32.u64 %0, t; }" : "=r"(a) : "l"(p));
    return a;
}
__device__ __forceinline__ void cpasync16(uint32_t dst, const void* src) {
    asm volatile("cp.async.cg.shared.global [%0], [%1], 16;" :: "r"(dst), "l"(src));
}
#define CP_COMMIT() asm volatile("cp.async.commit_group;" ::: "memory")
#define CP_WAIT(N)  asm volatile("cp.async.wait_group %0;" :: "n"(N) : "memory")

// ---------------- prep: one block per (roi, 32-channel chunk) + weight blocks --
__global__ void prep_all(const float* __restrict__ rois,
                         const float* __restrict__ wq, const float* __restrict__ wk,
                         const float* __restrict__ wv, const float* __restrict__ wre) {
    if (blockIdx.x >= 1024) {
        int base = (blockIdx.x - 1024) * 1024 + threadIdx.x;
#pragma unroll
        for (int i = 0; i < 4; i++) {
            int t = base + i * 256;
            int o = t >> 8, c = t & 255;
            int cperm = (c & ~15) | perm16(c & 15);
            g_wqh[o * C_IN + cperm] = __float2half_rn(wq[t] * LOG2E);
            g_wkh[o * C_IN + cperm] = __float2half_rn(wk[t]);
            g_wvh[o * C_IN + cperm] = __float2half_rn(wv[t]);
            int co = t >> 7, h = t & 127;
            int hperm = (h & ~15) | perm16(h & 15);
            g_wreh[wre_off(co, hperm)] = __float2half_rn(wre[t]);
        }
        return;
    }
    __shared__ float t[32][197];
    const int n  = blockIdx.x >> 3;
    const int c0 = (blockIdx.x & 7) * 32;
    const int tid = threadIdx.x;

    for (int e = tid; e < 32 * HW; e += 256) {
        int ci = e / HW, p = e - ci * HW;
        t[ci][p] = rois[(n * C_IN + c0 + ci) * HW + p];
    }
    __syncthreads();
    for (int e = tid; e < HW * 16; e += 256) {
        int p = e >> 4, cp = e & 15;
        int P = (c0 >> 1) + cp;
        int q = P & 7;
        int P2 = (P & ~7) | ((q < 4) ? (2 * q) : (2 * (q - 4) + 1));
        __half2 h = __floats2half2_rn(t[2 * cp][p], t[2 * cp + 1][p]);
        ((__half2*)g_Aq)[(size_t)(n * HW + p) * 128 + P2] = h;
    }
    for (int e = tid; e < PHW * 16; e += 256) {
        int pp = e >> 4, cp = e & 15;
        int py = pp / 7, px = pp - py * 7;
        int base = py * 28 + px * 2;
        float a0 = fmaxf(fmaxf(t[2 * cp][base], t[2 * cp][base + 1]),
                         fmaxf(t[2 * cp][base + 14], t[2 * cp][base + 15]));
        float a1 = fmaxf(fmaxf(t[2 * cp + 1][base], t[2 * cp + 1][base + 1]),
                         fmaxf(t[2 * cp + 1][base + 14], t[2 * cp + 1][base + 15]));
        int P = (c0 >> 1) + cp;
        int q = P & 7;
        int P2 = (P & ~7) | ((q < 4) ? (2 * q) : (2 * (q - 4) + 1));
        ((__half2*)g_Ap)[(size_t)(n * PHW + pp) * 128 + P2] = __floats2half2_rn(a0, a1);
    }
}

// ---------------- fused QKV projection GEMM (fp16 HMMA, uint2 frags) -----------
#define PJ_STRIDE 80
#define PJ_BUF    (128 * PJ_STRIDE)
#define PJ_VST    130
#define PJ_SMEM   (2 * PJ_BUF * 2)     // 40960 B

__global__ void __launch_bounds__(256, 4) proj_mma(const float* __restrict__ bq,
                                                   const float* __restrict__ bk,
                                                   const float* __restrict__ bv) {
    extern __shared__ __half psm[];
    const uint32_t psa = smem_u32(psm);

    int bx = blockIdx.x;
    int which, t0;
    if (bx < 196)      { which = 0; t0 = bx; }
    else if (bx < 245) { which = 1; t0 = bx - 196; }
    else               { which = 2; t0 = bx - 245; }
    const __half* A    = which ? g_Ap : g_Aq;
    const __half* W    = which == 0 ? g_wqh : (which == 1 ? g_wkh : g_wvh);
    const float*  bias = which == 0 ? bq    : (which == 1 ? bk    : bv);
    const float   bscale = which == 0 ? LOG2E : 1.0f;
    const int m0 = t0 * 128;

    const int tid  = threadIdx.x;
    const int warp = tid >> 5;
    const int lane = tid & 31;
    const int gr   = lane >> 2;
    const int tg   = lane & 3;
    const int qrow = warp * 16;

    {
        const __half* src = A + (size_t)m0 * C_IN;
#pragma unroll
        for (int i = 0; i < 4; i++) {
            int e = tid + i * 256;
            int row = e >> 3, seg = e & 7;
            cpasync16(psa + (row * PJ_STRIDE + seg * 8) * 2, src + (size_t)row * C_IN + seg * 8);
        }
        CP_COMMIT();
    }

    float y[16][4];
#pragma unroll
    for (int nt = 0; nt < 16; nt++)
#pragma unroll
        for (int j = 0; j < 4; j++) y[nt][j] = 0.f;

    for (int kc = 0; kc < 4; kc++) {
        CP_WAIT(0);
        __syncthreads();
        const __half* sA = psm + (kc & 1) * PJ_BUF;
        if (kc < 3) {
            const __half* src = A + (size_t)m0 * C_IN + (kc + 1) * 64;
            uint32_t dstb = psa + ((kc + 1) & 1) * (PJ_BUF * 2);
#pragma unroll
            for (int i = 0; i < 4; i++) {
                int e = tid + i * 256;
                int row = e >> 3, seg = e & 7;
                cpasync16(dstb + (row * PJ_STRIDE + seg * 8) * 2, src + (size_t)row * C_IN + seg * 8);
            }
            CP_COMMIT();
        }
#pragma unroll
        for (int ks = 0; ks < 4; ks++) {
            int k = kc * 64 + ks * 16;
            uint2 av0 = *(const uint2*)&sA[(qrow + gr) * PJ_STRIDE + ks * 16 + 4 * tg];
            uint2 av1 = *(const uint2*)&sA[(qrow + gr + 8) * PJ_STRIDE + ks * 16 + 4 * tg];
#pragma unroll
            for (int nt = 0; nt < 16; nt++) {
                int o = nt * 8 + gr;
                uint2 wv2 = *(const uint2*)&W[(size_t)o * C_IN + k + 4 * tg];
                mma_f16(y[nt][0], y[nt][1], y[nt][2], y[nt][3],
                        av0.x, av1.x, av0.y, av1.y, wv2.x, wv2.y);
            }
        }
        __syncthreads();
    }

    if (which == 0) {
#pragma unroll
        for (int nt = 0; nt < 16; nt++) {
            int o  = nt * 8 + 2 * tg;
            int hp = (nt >> 1) * 16 + 4 * tg + 2 * (nt & 1);
            float bb0 = bias[o] * bscale, bb1 = bias[o + 1] * bscale;
            *(__half2*)&g_qh[(size_t)(m0 + qrow + gr) * HID + hp] =
                __floats2half2_rn(y[nt][0] + bb0, y[nt][1] + bb1);
            *(__half2*)&g_qh[(size_t)(m0 + qrow + gr + 8) * HID + hp] =
                __floats2half2_rn(y[nt][2] + bb0, y[nt][3] + bb1);
        }
    } else if (which == 1) {
        int m1 = m0 + qrow + gr;
        int m2 = m1 + 8;
        int bb1_ = (m1 >= NK_B), bb2_ = (m2 >= NK_B);
        int key1 = m1 - bb1_ * NK_B, key2 = m2 - bb2_ * NK_B;
        __half* c1 = g_kh + (size_t)(bb1_ * 49 + (key1 >> 6)) * 8192;
        __half* c2 = g_kh + (size_t)(bb2_ * 49 + (key2 >> 6)) * 8192;
        int kk1 = key1 & 63, kk2 = key2 & 63;
#pragma unroll
        for (int nt = 0; nt < 16; nt++) {
            int o  = nt * 8 + 2 * tg;
            int hp = (nt >> 1) * 16 + 4 * tg + 2 * (nt & 1);
            float bb0 = bias[o], bb1 = bias[o + 1];
            *(__half2*)&c1[ak_off(kk1, hp)] = __floats2half2_rn(y[nt][0] + bb0, y[nt][1] + bb1);
            *(__half2*)&c2[ak_off(kk2, hp)] = __floats2half2_rn(y[nt][2] + bb0, y[nt][3] + bb1);
        }
    } else {
        __half* sV = psm;
#pragma unroll
        for (int nt = 0; nt < 16; nt++) {
            int o = nt * 8 + 2 * tg;
            float bb0 = bias[o], bb1 = bias[o + 1];
            sV[(qrow + gr) * PJ_VST + o]         = __float2half_rn(y[nt][0] + bb0);
            sV[(qrow + gr) * PJ_VST + o + 1]     = __float2half_rn(y[nt][1] + bb1);
            sV[(qrow + gr + 8) * PJ_VST + o]     = __float2half_rn(y[nt][2] + bb0);
            sV[(qrow + gr + 8) * PJ_VST + o + 1] = __float2half_rn(y[nt][3] + bb1);
        }
        __syncthreads();
#pragma unroll
        for (int i = 0; i < 64; i++) {
            int e = tid + i * 256;
            int h = e >> 7, kk0 = e & 127;
            int m = m0 + kk0;
            int bb = (m >= NK_B) ? 1 : 0;
            int key = m - bb * NK_B;
            int kk = key & 63;
            int kkp = (kk & ~15) | perm16(kk & 15);
            g_vTh[(size_t)(bb * 49 + (key >> 6)) * 8192 + av_off(h, kkp)] = sV[kk0 * PJ_VST + h];
        }
    }
}

// ---------------- fp16 HMMA flash attention + fused epilogue (BQ=64) -----------
#define SK_BUF_H   8192
#define SV_BUF_H   8192
#define SM_V_H     (2 * SK_BUF_H)
#define ATTN_SMEM  ((SM_V_H + 2 * SV_BUF_H) * 2)   // 65536 B
#define ED_STRIDE  129

__global__ void __launch_bounds__(128, 2) attn_mma_kernel(const float* __restrict__ rois,
                                                          const float* __restrict__ bre,
                                                          float* __restrict__ out) {
    extern __shared__ __half smh[];
    __half* sK  = smh;
    __half* sVt = smh + SM_V_H;
    float*  sD  = (float*)smh;
    const uint32_t sKa  = smem_u32(sK);
    const uint32_t sVta = smem_u32(sVt);

    const int tid  = threadIdx.x;
    const int warp = tid >> 5;
    const int lane = tid & 31;
    const int gr   = lane >> 2;
    const int tg   = lane & 3;
    const int b    = blockIdx.y;
    const int q0   = blockIdx.x * 64;
    const int qrow = warp * 16;

    const __half* qb = g_qh + (size_t)(b * NQ_B + q0 + qrow) * HID;
    uint32_t qf[8][4];
#pragma unroll
    for (int ks = 0; ks < 8; ks++) {
        uint2 v0 = *(const uint2*)(qb + (size_t)gr * HID + ks * 16 + 4 * tg);
        uint2 v1 = *(const uint2*)(qb + (size_t)(gr + 8) * HID + ks * 16 + 4 * tg);
        qf[ks][0] = v0.x; qf[ks][2] = v0.y;
        qf[ks][1] = v1.x; qf[ks][3] = v1.y;
    }

    const __half* kb0 = g_kh + (size_t)(b * 49) * 8192;
    const __half* vb0 = g_vTh + (size_t)(b * 49) * 8192;

#pragma unroll
    for (int i = 0; i < 8; i++) {
        int e = tid + i * 128;
        cpasync16(sKa + e * 16, kb0 + e * 8);
    }
#pragma unroll
    for (int i = 0; i < 8; i++) {
        int e = tid + i * 128;
        cpasync16(sVta + e * 16, vb0 + e * 8);
    }
    CP_COMMIT();

    float y[16][4];
#pragma unroll
    for (int nt = 0; nt < 16; nt++)
#pragma unroll
        for (int j = 0; j < 4; j++) y[nt][j] = 0.f;
    float m0 = -INFINITY, m1 = -INFINITY;
    float lsum0 = 0.f, lsum1 = 0.f;

    for (int kc = 0; kc < 49; kc++) {
        CP_WAIT(0);
        __syncthreads();

        if (kc < 48) {
            const __half* kb = kb0 + (size_t)(kc + 1) * 8192;
            const __half* vb = vb0 + (size_t)(kc + 1) * 8192;
            uint32_t kdst = sKa + ((kc + 1) & 1) * (SK_BUF_H * 2);
            uint32_t vdst = sVta + ((kc + 1) & 1) * (SV_BUF_H * 2);
#pragma unroll
            for (int i = 0; i < 8; i++) {
                int e = tid + i * 128;
                cpasync16(kdst + e * 16, kb + e * 8);
            }
#pragma unroll
            for (int i = 0; i < 8; i++) {
                int e = tid + i * 128;
                cpasync16(vdst + e * 16, vb + e * 8);
            }
            CP_COMMIT();
        }

        const uint4* sK4 = (const uint4*)(sK + (kc & 1) * SK_BUF_H);
        const uint4* sV4 = (const uint4*)(sVt + (kc & 1) * SV_BUF_H);

        // ---- S = Q K^T : uint4 -> 2 MMAs ----
        float s[8][4];
#pragma unroll
        for (int nt = 0; nt < 8; nt++)
#pragma unroll
            for (int j = 0; j < 4; j++) s[nt][j] = 0.f;
#pragma unroll
        for (int ks = 0; ks < 8; ks++) {
#pragma unroll
            for (int ntp = 0; ntp < 4; ntp++) {
                uint4 kv = sK4[(ks * 4 + ntp) * 32 + lane];
                mma_f16(s[2 * ntp][0], s[2 * ntp][1], s[2 * ntp][2], s[2 * ntp][3],
                        qf[ks][0], qf[ks][1], qf[ks][2], qf[ks][3], kv.x, kv.y);
                mma_f16(s[2 * ntp + 1][0], s[2 * ntp + 1][1], s[2 * ntp + 1][2], s[2 * ntp + 1][3],
                        qf[ks][0], qf[ks][1], qf[ks][2], qf[ks][3], kv.z, kv.w);
            }
        }

        // ---- running row max (base-2), conditional rescale ----
        float mx0 = -INFINITY, mx1 = -INFINITY;
#pragma unroll
        for (int nt = 0; nt < 8; nt++) {
            mx0 = fmaxf(mx0, fmaxf(s[nt][0], s[nt][1]));
            mx1 = fmaxf(mx1, fmaxf(s[nt][2], s[nt][3]));
        }
        mx0 = fmaxf(mx0, __shfl_xor_sync(0xffffffffu, mx0, 1));
        mx0 = fmaxf(mx0, __shfl_xor_sync(0xffffffffu, mx0, 2));
        mx1 = fmaxf(mx1, __shfl_xor_sync(0xffffffffu, mx1, 1));
        mx1 = fmaxf(mx1, __shfl_xor_sync(0xffffffffu, mx1, 2));
        bool grew = (mx0 > m0) || (mx1 > m1);
        if (__any_sync(0xffffffffu, grew)) {
            float mn0 = fmaxf(m0, mx0);
            float mn1 = fmaxf(m1, mx1);
            float corr0 = exp2f(m0 - mn0);
            float corr1 = exp2f(m1 - mn1);
            m0 = mn0; m1 = mn1;
            lsum0 *= corr0; lsum1 *= corr1;
#pragma unroll
            for (int nt = 0; nt < 16; nt++) {
                y[nt][0] *= corr0; y[nt][1] *= corr0;
                y[nt][2] *= corr1; y[nt][3] *= corr1;
            }
        }

        // ---- P = exp2(S - m) via ex2.approx.f16x2; lsum from same fp16 values --
        uint32_t pa[4][4];
#pragma unroll
        for (int nt = 0; nt < 8; nt++) {
            uint32_t h01 = h2exp2(s[nt][0] - m0, s[nt][1] - m0);
            uint32_t h23 = h2exp2(s[nt][2] - m1, s[nt][3] - m1);
            float2 f01 = __half22float2(*(__half2*)&h01);
            float2 f23 = __half22float2(*(__half2*)&h23);
            lsum0 += f01.x + f01.y;
            lsum1 += f23.x + f23.y;
            int kp = nt >> 1;
            if ((nt & 1) == 0) { pa[kp][0] = h01; pa[kp][1] = h23; }
            else               { pa[kp][2] = h01; pa[kp][3] = h23; }
        }

        // ---- Y += P V : uint4 -> 2 MMAs ----
#pragma unroll
        for (int ks = 0; ks < 4; ks++) {
#pragma unroll
            for (int ntp = 0; ntp < 8; ntp++) {
                uint4 vv = sV4[(ks * 8 + ntp) * 32 + lane];
                mma_f16(y[2 * ntp][0], y[2 * ntp][1], y[2 * ntp][2], y[2 * ntp][3],
                        pa[ks][0], pa[ks][1], pa[ks][2], pa[ks][3], vv.x, vv.y);
                mma_f16(y[2 * ntp + 1][0], y[2 * ntp + 1][1], y[2 * ntp + 1][2], y[2 * ntp + 1][3],
                        pa[ks][0], pa[ks][1], pa[ks][2], pa[ks][3], vv.z, vv.w);
            }
        }
    }

#pragma unroll
    for (int off = 1; off < 4; off <<= 1) {
        lsum0 += __shfl_xor_sync(0xffffffffu, lsum0, off);
        lsum1 += __shfl_xor_sync(0xffffffffu, lsum1, off);
    }
    const float inv0 = 1.0f / lsum0;
    const float inv1 = 1.0f / lsum1;

    uint32_t pya[8][4];
#pragma unroll
    for (int ks = 0; ks < 8; ks++) {
        __half2 h0 = __floats2half2_rn(y[2 * ks][0] * inv0, y[2 * ks][1] * inv0);
        __half2 h1 = __floats2half2_rn(y[2 * ks][2] * inv1, y[2 * ks][3] * inv1);
        __half2 h2 = __floats2half2_rn(y[2 * ks + 1][0] * inv0, y[2 * ks + 1][1] * inv0);
        __half2 h3 = __floats2half2_rn(y[2 * ks + 1][2] * inv1, y[2 * ks + 1][3] * inv1);
        pya[ks][0] = *(uint32_t*)&h0;
        pya[ks][1] = *(uint32_t*)&h1;
        pya[ks][2] = *(uint32_t*)&h2;
        pya[ks][3] = *(uint32_t*)&h3;
    }

    __syncthreads();

    const int mb = b * NQ_B + q0;
    const uint4* w4 = (const uint4*)g_wreh;
#pragma unroll 1
    for (int half = 0; half < 2; half++) {
        const int n0 = half * 128;

        float ye[16][4];
#pragma unroll
        for (int nt = 0; nt < 16; nt++)
#pragma unroll
            for (int j = 0; j < 4; j++) ye[nt][j] = 0.f;

#pragma unroll
        for (int ks = 0; ks < 8; ks++) {
#pragma unroll
            for (int ntp = 0; ntp < 8; ntp++) {
                uint4 wv = w4[(((size_t)half * 8 + ks) * 8 + ntp) * 32 + lane];
                mma_f16(ye[2 * ntp][0], ye[2 * ntp][1], ye[2 * ntp][2], ye[2 * ntp][3],
                        pya[ks][0], pya[ks][1], pya[ks][2], pya[ks][3], wv.x, wv.y);
                mma_f16(ye[2 * ntp + 1][0], ye[2 * ntp + 1][1], ye[2 * ntp + 1][2], ye[2 * ntp + 1][3],
                        pya[ks][0], pya[ks][1], pya[ks][2], pya[ks][3], wv.z, wv.w);
            }
        }

#pragma unroll
        for (int nt = 0; nt < 16; nt++) {
            int o = nt * 8 + 2 * tg;
            sD[(qrow + gr) * ED_STRIDE + o]         = ye[nt][0];
            sD[(qrow + gr) * ED_STRIDE + o + 1]     = ye[nt][1];
            sD[(qrow + gr + 8) * ED_STRIDE + o]     = ye[nt][2];
            sD[(qrow + gr + 8) * ED_STRIDE + o + 1] = ye[nt][3];
        }
        __syncthreads();

#pragma unroll 4
        for (int i = 0; i < 64; i++) {
            int e = tid + i * 128;
            int o = e >> 6, ml = e & 63;
            int mg = mb + ml;
            int n = mg / HW;
            int p = mg - n * HW;
            int co = n0 + o;
            size_t idx = (size_t)(n * C_IN + co) * HW + p;
            out[idx] = rois[idx] + sD[ml * ED_STRIDE + o] + bre[co];
        }
        __syncthreads();
    }
}

// ---------------- launch ------------------------------------------------------
extern "C" void kernel_launch(void* const* d_in, const int* in_sizes, int n_in,
                              void* d_out, int out_size) {
    const float* rois = (const float*)d_in[0];
    const float* wq  = (const float*)d_in[2];
    const float* bq  = (const float*)d_in[3];
    const float* wk  = (const float*)d_in[4];
    const float* bk  = (const float*)d_in[5];
    const float* wv  = (const float*)d_in[6];
    const float* bv  = (const float*)d_in[7];
    const float* wre = (const float*)d_in[8];
    const float* bre = (const float*)d_in[9];
    float* out = (float*)d_out;

    cudaFuncSetAttribute(attn_mma_kernel, cudaFuncAttributeMaxDynamicSharedMemorySize, ATTN_SMEM);
    cudaFuncSetAttribute(proj_mma, cudaFuncAttributeMaxDynamicSharedMemorySize, PJ_SMEM);

    prep_all<<<1056, 256>>>(rois, wq, wk, wv, wre);
    proj_mma<<<294, 256, PJ_SMEM>>>(bq, bk, bv);
    attn_mma_kernel<<<dim3(196, 2), 128, ATTN_SMEM>>>(rois, bre, out);
}